// round 2
// baseline (speedup 1.0000x reference)
#include <cuda_runtime.h>
#include <math.h>

// Problem constants (fixed shapes)
#define B_  4
#define C_  32      // C_IN == C_OUT == 32
#define T_  48
#define N_  2000
#define E_  16000
#define BT_ (B_ * T_)    // 192

// ---------------------------------------------------------------------------
// Scratch (device globals — no runtime allocation allowed)
// ---------------------------------------------------------------------------
__device__ float g_xw[BT_ * N_ * C_];    // xw = relu(conv1(x)) @ gcn_w, layout [g][n][c]
__device__ float g_gout[BT_ * N_ * C_];  // GCN output, layout [g][n][c]
__device__ int   g_src[E_];
__device__ int   g_dst[E_];
__device__ int   g_cnt[N_];
__device__ int   g_cur[N_];
__device__ int   g_off[N_ + 1];
__device__ int   g_csr_src[E_];
__device__ float g_csr_w[E_];
__device__ float g_dinv[N_];
__device__ float g_invdeg[N_];

// ---------------------------------------------------------------------------
// Edge preprocessing: dtype-detect (int64 vs int32), convert, histogram,
// prefix-scan -> CSR offsets + degree terms, CSR fill.
// ---------------------------------------------------------------------------
__global__ void k_convert(const void* __restrict__ edges) {
    __shared__ int s_is64;
    if (threadIdx.x == 0) {
        // If edge_index is int64, the high 32-bit word of every (small,
        // non-negative) entry is zero. If int32, odd words are src values
        // in [0,2000) — all-zero over 64 samples has ~0 probability.
        const int* q = (const int*)edges;
        int ok = 1;
        #pragma unroll 1
        for (int i = 0; i < 64; i++) {
            if (q[2 * i + 1] != 0) { ok = 0; break; }
        }
        s_is64 = ok;
    }
    __syncthreads();
    int e = blockIdx.x * blockDim.x + threadIdx.x;
    if (e >= E_) return;
    int s, d;
    if (s_is64) {
        const long long* p = (const long long*)edges;
        s = (int)p[e];
        d = (int)p[E_ + e];
    } else {
        const int* p = (const int*)edges;
        s = p[e];
        d = p[E_ + e];
    }
    g_src[e] = s;
    g_dst[e] = d;
}

__global__ void k_zero_counts() {
    int i = blockIdx.x * blockDim.x + threadIdx.x;
    if (i < N_) g_cnt[i] = 0;
    else if (i < 2 * N_) g_cur[i - N_] = 0;
}

__global__ void k_hist() {
    int e = blockIdx.x * blockDim.x + threadIdx.x;
    if (e >= E_) return;
    atomicAdd(&g_cnt[g_dst[e]], 1);
}

// Single-block scan over N_=2000 counters; also degree terms.
__global__ void k_scan() {
    __shared__ int psum[256];
    const int CH = 8;   // 256*8 = 2048 >= 2000
    int tid = threadIdx.x;
    int base = tid * CH;
    int c[CH];
    int s = 0;
    #pragma unroll
    for (int i = 0; i < CH; i++) {
        int idx = base + i;
        c[i] = (idx < N_) ? g_cnt[idx] : 0;
        s += c[i];
    }
    psum[tid] = s;
    __syncthreads();
    if (tid == 0) {
        int run = 0;
        #pragma unroll 1
        for (int i = 0; i < 256; i++) { int v = psum[i]; psum[i] = run; run += v; }
    }
    __syncthreads();
    int run = psum[tid];
    #pragma unroll
    for (int i = 0; i < CH; i++) {
        int idx = base + i;
        if (idx < N_) {
            g_off[idx] = run;
            float deg = (float)c[i] + 1.0f;
            g_dinv[idx]   = rsqrtf(deg);
            g_invdeg[idx] = 1.0f / deg;
        }
        run += c[i];
    }
    if (tid == 255) g_off[N_] = run;   // == E_
}

__global__ void k_fill() {
    int e = blockIdx.x * blockDim.x + threadIdx.x;
    if (e >= E_) return;
    int d = g_dst[e];
    int s = g_src[e];
    int pos = atomicAdd(&g_cur[d], 1);
    int idx = g_off[d] + pos;
    g_csr_src[idx] = s;
    g_csr_w[idx] = g_dinv[s] * g_dinv[d];
}

// ---------------------------------------------------------------------------
// K1: fused  xw = relu(conv1(x) + b1) @ gcn_w
//     x: [B, C, T, N],  output g_xw: [g=b*T+t][n][c]  (c contiguous)
// One thread per (b, t, n); h[32] and o[32] in registers; weights in smem
// read as broadcast float4.
// ---------------------------------------------------------------------------
__global__ void __launch_bounds__(128) k_conv1_gemm(
    const float* __restrict__ x,
    const float* __restrict__ w1,
    const float* __restrict__ b1,
    const float* __restrict__ gcn_w)
{
    __shared__ float w1s[C_ * 3 * C_];   // [(ci*3+k)*32 + co]
    __shared__ float gws[C_ * C_];       // [co*32 + c2]
    __shared__ float b1s[C_];

    int tid = threadIdx.x;
    for (int i = tid; i < C_ * 3 * C_; i += blockDim.x) {
        int co = i & 31;
        int rest = i >> 5;
        int k = rest % 3;
        int ci = rest / 3;
        w1s[i] = w1[(co * C_ + ci) * 3 + k];
    }
    for (int i = tid; i < C_ * C_; i += blockDim.x) gws[i] = gcn_w[i];
    if (tid < C_) b1s[tid] = b1[tid];
    __syncthreads();

    int n = blockIdx.x * blockDim.x + tid;
    int t = blockIdx.y;
    int b = blockIdx.z;
    if (n >= N_) return;

    float h[C_];
    #pragma unroll
    for (int co = 0; co < C_; co++) h[co] = b1s[co];

    #pragma unroll 1
    for (int ci = 0; ci < C_; ci++) {
        const float* xp = x + (((b * C_ + ci) * T_) + t) * N_ + n;
        #pragma unroll
        for (int k = 0; k < 3; k++) {
            int tt = t + k - 1;
            if (tt < 0 || tt >= T_) continue;
            float xv = xp[(k - 1) * N_];
            const float4* wp = reinterpret_cast<const float4*>(&w1s[(ci * 3 + k) * C_]);
            #pragma unroll
            for (int q = 0; q < 8; q++) {
                float4 w = wp[q];
                h[4 * q + 0] += w.x * xv;
                h[4 * q + 1] += w.y * xv;
                h[4 * q + 2] += w.z * xv;
                h[4 * q + 3] += w.w * xv;
            }
        }
    }

    float o[C_];
    #pragma unroll
    for (int c = 0; c < C_; c++) o[c] = 0.0f;

    #pragma unroll 1
    for (int co = 0; co < C_; co++) {
        float hv = fmaxf(h[co], 0.0f);
        const float4* gp = reinterpret_cast<const float4*>(&gws[co * C_]);
        #pragma unroll
        for (int q = 0; q < 8; q++) {
            float4 w = gp[q];
            o[4 * q + 0] += w.x * hv;
            o[4 * q + 1] += w.y * hv;
            o[4 * q + 2] += w.z * hv;
            o[4 * q + 3] += w.w * hv;
        }
    }

    float* op = g_xw + (((b * T_ + t) * N_) + n) * C_;
    #pragma unroll
    for (int q = 0; q < 8; q++) {
        float4 st;
        st.x = o[4 * q + 0];
        st.y = o[4 * q + 1];
        st.z = o[4 * q + 2];
        st.w = o[4 * q + 3];
        reinterpret_cast<float4*>(op)[q] = st;
    }
}

// ---------------------------------------------------------------------------
// K2: GCN aggregation via CSR. One warp per (graph, dst-node); lane = channel.
// gout[g,n,c] = sum_{e in row(n)} w_e * xw[g, src_e, c]
//             + invdeg[n] * xw[g,n,c] + gcn_b[c]
// ---------------------------------------------------------------------------
__global__ void __launch_bounds__(256) k_agg(const float* __restrict__ gcn_b) {
    int warp = threadIdx.x >> 5;
    int lane = threadIdx.x & 31;
    int n = blockIdx.x * 8 + warp;
    int g = blockIdx.y;
    if (n >= N_) return;

    int s0 = g_off[n];
    int s1 = g_off[n + 1];
    const float* xwg = g_xw + (size_t)g * N_ * C_;

    float acc = 0.0f;
    #pragma unroll 1
    for (int e = s0; e < s1; e++) {
        int s = g_csr_src[e];
        float w = g_csr_w[e];
        acc += w * xwg[s * C_ + lane];
    }
    acc += g_invdeg[n] * xwg[n * C_ + lane] + gcn_b[lane];
    g_gout[(size_t)g * N_ * C_ + n * C_ + lane] = acc;
}

// ---------------------------------------------------------------------------
// K3: conv2 over gout [g][n][c] -> out [B, C, T, N]
// One thread per (b, t, n) computing all 32 output channels.
// ---------------------------------------------------------------------------
__global__ void __launch_bounds__(128) k_conv2(
    const float* __restrict__ w2,
    const float* __restrict__ b2,
    float* __restrict__ out)
{
    __shared__ float w2s[C_ * 3 * C_];   // [(ci*3+k)*32 + co]
    __shared__ float b2s[C_];

    int tid = threadIdx.x;
    for (int i = tid; i < C_ * 3 * C_; i += blockDim.x) {
        int co = i & 31;
        int rest = i >> 5;
        int k = rest % 3;
        int ci = rest / 3;
        w2s[i] = w2[(co * C_ + ci) * 3 + k];
    }
    if (tid < C_) b2s[tid] = b2[tid];
    __syncthreads();

    int n = blockIdx.x * blockDim.x + tid;
    int t = blockIdx.y;
    int b = blockIdx.z;
    if (n >= N_) return;

    float o[C_];
    #pragma unroll
    for (int co = 0; co < C_; co++) o[co] = b2s[co];

    #pragma unroll
    for (int k = 0; k < 3; k++) {
        int tt = t + k - 1;
        if (tt < 0 || tt >= T_) continue;
        const float4* gp = reinterpret_cast<const float4*>(
            g_gout + (((b * T_ + tt) * N_) + n) * C_);
        #pragma unroll
        for (int q4 = 0; q4 < 8; q4++) {
            float4 gv = gp[q4];
            float xv[4] = {gv.x, gv.y, gv.z, gv.w};
            #pragma unroll
            for (int j = 0; j < 4; j++) {
                int ci = q4 * 4 + j;
                const float4* wp = reinterpret_cast<const float4*>(&w2s[(ci * 3 + k) * C_]);
                float v = xv[j];
                #pragma unroll
                for (int q = 0; q < 8; q++) {
                    float4 w = wp[q];
                    o[4 * q + 0] += w.x * v;
                    o[4 * q + 1] += w.y * v;
                    o[4 * q + 2] += w.z * v;
                    o[4 * q + 3] += w.w * v;
                }
            }
        }
    }

    #pragma unroll
    for (int co = 0; co < C_; co++) {
        out[(((b * C_ + co) * T_) + t) * N_ + n] = o[co];
    }
}

// ---------------------------------------------------------------------------
// Launcher
// ---------------------------------------------------------------------------
extern "C" void kernel_launch(void* const* d_in, const int* in_sizes, int n_in,
                              void* d_out, int out_size) {
    const float* x     = (const float*)d_in[0];
    const void*  edges = d_in[1];
    const float* w1    = (const float*)d_in[2];
    const float* b1    = (const float*)d_in[3];
    const float* gcn_w = (const float*)d_in[4];
    const float* gcn_b = (const float*)d_in[5];
    const float* w2    = (const float*)d_in[6];
    const float* b2    = (const float*)d_in[7];
    float* out = (float*)d_out;

    // Edge preprocessing -> CSR (all tiny)
    k_convert<<<(E_ + 255) / 256, 256>>>(edges);
    k_zero_counts<<<(2 * N_ + 255) / 256, 256>>>();
    k_hist<<<(E_ + 255) / 256, 256>>>();
    k_scan<<<1, 256>>>();
    k_fill<<<(E_ + 255) / 256, 256>>>();

    // Main pipeline
    dim3 gconv((N_ + 127) / 128, T_, B_);
    k_conv1_gemm<<<gconv, 128>>>(x, w1, b1, gcn_w);

    dim3 gagg(N_ / 8, BT_);
    k_agg<<<gagg, 256>>>(gcn_b);

    k_conv2<<<gconv, 128>>>(w2, b2, out);
}

// round 3
// speedup vs baseline: 1.0910x; 1.0910x over previous
#include <cuda_runtime.h>
#include <math.h>

// Problem constants (fixed shapes)
#define B_  4
#define C_  32      // C_IN == C_OUT == 32
#define T_  48
#define N_  2000
#define E_  16000
#define BT_ (B_ * T_)    // 192

// ---------------------------------------------------------------------------
// Scratch (device globals — no runtime allocation allowed)
// ---------------------------------------------------------------------------
__device__ float g_xw[BT_ * N_ * C_];    // xw = relu(conv1(x)) @ gcn_w, layout [g][n][c]
__device__ float g_gout[BT_ * N_ * C_];  // GCN output, layout [g][n][c]
__device__ int   g_off[N_ + 1];
__device__ int   g_csr_src[E_];
__device__ float g_csr_w[E_];
__device__ float g_invdeg[N_];

// ---------------------------------------------------------------------------
// f32x2 packed-math helpers (Blackwell FFMA2: 2 fp32 FMA per issue slot)
// ---------------------------------------------------------------------------
__device__ __forceinline__ unsigned long long dup2(float x) {
    unsigned long long r;
    unsigned u = __float_as_uint(x);
    asm("mov.b64 %0, {%1, %1};" : "=l"(r) : "r"(u));
    return r;
}
__device__ __forceinline__ void ffma2(unsigned long long& acc,
                                      unsigned long long a,
                                      unsigned long long b) {
    asm("fma.rn.f32x2 %0, %1, %2, %0;" : "+l"(acc) : "l"(a), "l"(b));
}
__device__ __forceinline__ float2 unpack2(unsigned long long v) {
    unsigned lo, hi;
    asm("mov.b64 {%0, %1}, %2;" : "=r"(lo), "=r"(hi) : "l"(v));
    return make_float2(__uint_as_float(lo), __uint_as_float(hi));
}

// ---------------------------------------------------------------------------
// Single-kernel edge preprocessing: dtype-detect, histogram (smem atomics),
// block scan -> CSR offsets + degree terms, CSR fill. One block, 1024 threads.
// Edges live in registers between phases.
// ---------------------------------------------------------------------------
__global__ void __launch_bounds__(1024) k_prep(const void* __restrict__ edges) {
    __shared__ int   s_cnt[2048];
    __shared__ int   s_off[2048];
    __shared__ float s_dinv[2048];
    __shared__ int   s_wsum[32];
    __shared__ int   s_is64;

    int tid = threadIdx.x;
    if (tid == 0) {
        // int64 edge_index => high word of each small entry is 0.
        const int* q = (const int*)edges;
        int ok = 1;
        #pragma unroll 1
        for (int i = 0; i < 64; i++) {
            if (q[2 * i + 1] != 0) { ok = 0; break; }
        }
        s_is64 = ok;
    }
    s_cnt[tid] = 0;
    s_cnt[tid + 1024] = 0;
    __syncthreads();

    const int is64 = s_is64;
    int es[16], ed[16];
    #pragma unroll
    for (int i = 0; i < 16; i++) {
        int e = tid + i * 1024;
        if (e < E_) {
            int s, d;
            if (is64) {
                const long long* p = (const long long*)edges;
                s = (int)p[e];
                d = (int)p[E_ + e];
            } else {
                const int* p = (const int*)edges;
                s = p[e];
                d = p[E_ + e];
            }
            es[i] = s; ed[i] = d;
            atomicAdd(&s_cnt[d], 1);
        } else {
            es[i] = -1; ed[i] = -1;
        }
    }
    __syncthreads();

    // Block exclusive scan over 2000 counts (2 per thread)
    int lane = tid & 31, wid = tid >> 5;
    int i0 = 2 * tid, i1 = 2 * tid + 1;
    int c0 = (i0 < N_) ? s_cnt[i0] : 0;
    int c1 = (i1 < N_) ? s_cnt[i1] : 0;
    int sum = c0 + c1;
    int incl = sum;
    #pragma unroll
    for (int o = 1; o < 32; o <<= 1) {
        int v = __shfl_up_sync(0xffffffffu, incl, o);
        if (lane >= o) incl += v;
    }
    if (lane == 31) s_wsum[wid] = incl;
    __syncthreads();
    if (wid == 0) {
        int w = s_wsum[lane];
        int wi = w;
        #pragma unroll
        for (int o = 1; o < 32; o <<= 1) {
            int v = __shfl_up_sync(0xffffffffu, wi, o);
            if (lane >= o) wi += v;
        }
        s_wsum[lane] = wi - w;   // exclusive
    }
    __syncthreads();
    int excl = s_wsum[wid] + incl - sum;
    if (i0 < N_) {
        s_off[i0] = excl;
        g_off[i0] = excl;
        float deg = (float)c0 + 1.0f;
        s_dinv[i0] = rsqrtf(deg);
        g_invdeg[i0] = 1.0f / deg;
    }
    if (i1 < N_) {
        int e1 = excl + c0;
        s_off[i1] = e1;
        g_off[i1] = e1;
        float deg = (float)c1 + 1.0f;
        s_dinv[i1] = rsqrtf(deg);
        g_invdeg[i1] = 1.0f / deg;
    }
    if (tid == 0) g_off[N_] = E_;
    __syncthreads();

    // reset cursors
    s_cnt[tid] = 0;
    s_cnt[tid + 1024] = 0;
    __syncthreads();

    // CSR fill
    #pragma unroll
    for (int i = 0; i < 16; i++) {
        if (ed[i] >= 0) {
            int d = ed[i], s = es[i];
            int pos = atomicAdd(&s_cnt[d], 1);
            int idx = s_off[d] + pos;
            g_csr_src[idx] = s;
            g_csr_w[idx] = s_dinv[s] * s_dinv[d];
        }
    }
}

// ---------------------------------------------------------------------------
// K1: fused  xw = relu(conv1(x) + b1) @ gcn_w   (FFMA2 throughout)
//     x: [B, C, T, N],  output g_xw: [g=b*T+t][n][c]  (c contiguous)
// ---------------------------------------------------------------------------
__global__ void __launch_bounds__(128) k_conv1_gemm(
    const float* __restrict__ x,
    const float* __restrict__ w1,
    const float* __restrict__ b1,
    const float* __restrict__ gcn_w)
{
    __shared__ __align__(16) float w1s[C_ * 3 * C_];   // [(ci*3+k)*32 + co]
    __shared__ __align__(16) float gws[C_ * C_];       // [co*32 + c2]
    __shared__ __align__(16) float b1s[C_];

    int tid = threadIdx.x;
    for (int i = tid; i < C_ * 3 * C_; i += blockDim.x) {
        int co = i & 31;
        int rest = i >> 5;
        int k = rest % 3;
        int ci = rest / 3;
        w1s[i] = w1[(co * C_ + ci) * 3 + k];
    }
    for (int i = tid; i < C_ * C_; i += blockDim.x) gws[i] = gcn_w[i];
    if (tid < C_) b1s[tid] = b1[tid];
    __syncthreads();

    int n = blockIdx.x * blockDim.x + tid;
    int t = blockIdx.y;
    int b = blockIdx.z;
    if (n >= N_) return;

    unsigned long long h2[16];
    const unsigned long long* bp = (const unsigned long long*)b1s;
    #pragma unroll
    for (int q = 0; q < 16; q++) h2[q] = bp[q];

    const float* xp0 = x + ((b * C_) * T_ + t) * N_ + n;
    #pragma unroll 2
    for (int ci = 0; ci < C_; ci++) {
        const float* xp = xp0 + ci * (T_ * N_);
        #pragma unroll
        for (int k = 0; k < 3; k++) {
            int tt = t + k - 1;
            if (tt < 0 || tt >= T_) continue;
            unsigned long long xv2 = dup2(xp[(k - 1) * N_]);
            const ulonglong2* wp = (const ulonglong2*)&w1s[(ci * 3 + k) * C_];
            #pragma unroll
            for (int q = 0; q < 8; q++) {
                ulonglong2 w = wp[q];
                ffma2(h2[2 * q + 0], w.x, xv2);
                ffma2(h2[2 * q + 1], w.y, xv2);
            }
        }
    }

    unsigned long long o2[16];
    #pragma unroll
    for (int q = 0; q < 16; q++) o2[q] = 0ull;

    #pragma unroll 1
    for (int q = 0; q < 16; q++) {
        float2 hp = unpack2(h2[q]);
        unsigned long long av = dup2(fmaxf(hp.x, 0.0f));
        unsigned long long bv = dup2(fmaxf(hp.y, 0.0f));
        const ulonglong2* ga = (const ulonglong2*)&gws[(2 * q + 0) * C_];
        const ulonglong2* gb = (const ulonglong2*)&gws[(2 * q + 1) * C_];
        #pragma unroll
        for (int j = 0; j < 8; j++) {
            ulonglong2 wa = ga[j];
            ffma2(o2[2 * j + 0], wa.x, av);
            ffma2(o2[2 * j + 1], wa.y, av);
        }
        #pragma unroll
        for (int j = 0; j < 8; j++) {
            ulonglong2 wb = gb[j];
            ffma2(o2[2 * j + 0], wb.x, bv);
            ffma2(o2[2 * j + 1], wb.y, bv);
        }
    }

    ulonglong2* op = (ulonglong2*)(g_xw + (((b * T_ + t) * N_) + n) * C_);
    #pragma unroll
    for (int j = 0; j < 8; j++) {
        ulonglong2 st;
        st.x = o2[2 * j + 0];
        st.y = o2[2 * j + 1];
        op[j] = st;
    }
}

// ---------------------------------------------------------------------------
// K2: GCN aggregation via CSR. One warp per (graph, dst-node); lane = channel.
// Dual accumulators for memory-level parallelism on the gather chain.
// ---------------------------------------------------------------------------
__global__ void __launch_bounds__(256) k_agg(const float* __restrict__ gcn_b) {
    int warp = threadIdx.x >> 5;
    int lane = threadIdx.x & 31;
    int n = blockIdx.x * 8 + warp;
    int g = blockIdx.y;
    if (n >= N_) return;

    int s0 = g_off[n];
    int s1 = g_off[n + 1];
    const float* __restrict__ xwg = g_xw + (size_t)g * N_ * C_;

    float accA = 0.0f, accB = 0.0f;
    int e = s0;
    for (; e + 1 < s1; e += 2) {
        int   sA = g_csr_src[e];
        int   sB = g_csr_src[e + 1];
        float wA = g_csr_w[e];
        float wB = g_csr_w[e + 1];
        float vA = __ldg(&xwg[sA * C_ + lane]);
        float vB = __ldg(&xwg[sB * C_ + lane]);
        accA += wA * vA;
        accB += wB * vB;
    }
    if (e < s1) {
        accA += g_csr_w[e] * __ldg(&xwg[g_csr_src[e] * C_ + lane]);
    }
    float acc = accA + accB + g_invdeg[n] * xwg[n * C_ + lane] + gcn_b[lane];
    g_gout[(size_t)g * N_ * C_ + n * C_ + lane] = acc;
}

// ---------------------------------------------------------------------------
// K3: conv2 over gout [g][n][c] -> out [B, C, T, N]   (FFMA2 throughout)
// ---------------------------------------------------------------------------
__global__ void __launch_bounds__(128) k_conv2(
    const float* __restrict__ w2,
    const float* __restrict__ b2,
    float* __restrict__ out)
{
    __shared__ __align__(16) float w2s[C_ * 3 * C_];   // [(ci*3+k)*32 + co]
    __shared__ __align__(16) float b2s[C_];

    int tid = threadIdx.x;
    for (int i = tid; i < C_ * 3 * C_; i += blockDim.x) {
        int co = i & 31;
        int rest = i >> 5;
        int k = rest % 3;
        int ci = rest / 3;
        w2s[i] = w2[(co * C_ + ci) * 3 + k];
    }
    if (tid < C_) b2s[tid] = b2[tid];
    __syncthreads();

    int n = blockIdx.x * blockDim.x + tid;
    int t = blockIdx.y;
    int b = blockIdx.z;
    if (n >= N_) return;

    unsigned long long o2[16];
    const unsigned long long* bp = (const unsigned long long*)b2s;
    #pragma unroll
    for (int q = 0; q < 16; q++) o2[q] = bp[q];

    #pragma unroll
    for (int k = 0; k < 3; k++) {
        int tt = t + k - 1;
        if (tt < 0 || tt >= T_) continue;
        const float4* gp = reinterpret_cast<const float4*>(
            g_gout + (((b * T_ + tt) * N_) + n) * C_);
        #pragma unroll 2
        for (int q4 = 0; q4 < 8; q4++) {
            float4 gv = gp[q4];
            float xv[4] = {gv.x, gv.y, gv.z, gv.w};
            #pragma unroll
            for (int j = 0; j < 4; j++) {
                int ci = q4 * 4 + j;
                unsigned long long v2 = dup2(xv[j]);
                const ulonglong2* wp = (const ulonglong2*)&w2s[(ci * 3 + k) * C_];
                #pragma unroll
                for (int q = 0; q < 8; q++) {
                    ulonglong2 w = wp[q];
                    ffma2(o2[2 * q + 0], w.x, v2);
                    ffma2(o2[2 * q + 1], w.y, v2);
                }
            }
        }
    }

    float* obase = out + ((b * C_) * T_ + t) * N_ + n;
    #pragma unroll
    for (int q = 0; q < 16; q++) {
        float2 v = unpack2(o2[q]);
        obase[(2 * q + 0) * (T_ * N_)] = v.x;
        obase[(2 * q + 1) * (T_ * N_)] = v.y;
    }
}

// ---------------------------------------------------------------------------
// Launcher
// ---------------------------------------------------------------------------
extern "C" void kernel_launch(void* const* d_in, const int* in_sizes, int n_in,
                              void* d_out, int out_size) {
    const float* x     = (const float*)d_in[0];
    const void*  edges = d_in[1];
    const float* w1    = (const float*)d_in[2];
    const float* b1    = (const float*)d_in[3];
    const float* gcn_w = (const float*)d_in[4];
    const float* gcn_b = (const float*)d_in[5];
    const float* w2    = (const float*)d_in[6];
    const float* b2    = (const float*)d_in[7];
    float* out = (float*)d_out;

    k_prep<<<1, 1024>>>(edges);

    dim3 gconv((N_ + 127) / 128, T_, B_);
    k_conv1_gemm<<<gconv, 128>>>(x, w1, b1, gcn_w);

    dim3 gagg(N_ / 8, BT_);
    k_agg<<<gagg, 256>>>(gcn_b);

    k_conv2<<<gconv, 128>>>(w2, b2, out);
}